// round 9
// baseline (speedup 1.0000x reference)
#include <cuda_runtime.h>
#include <cstdint>

#define EPS 1e-5f
#define NBATCH 16
#define GROUPS 4
#define BPG 4                                // batches per group (64MB)
#define PER4 (1024 * 1024)                   // float4s per batch = 1,048,576 (4M floats)

#define THREADS 512
#define NBLK 444                             // 3 blocks/SM x 148 SMs, co-resident
#define SLABS 111                            // 444 / BPG slabs per batch
#define SLAB_F4 ((PER4 + SLABS - 1) / SLABS) // 9447 float4 per slab (last slab short)
#define UN 4                                 // float4s per side per inner iteration

// Scratch (allocation-free -> __device__ globals, zero-initialized)
__device__ float        g_psum[NBATCH * SLABS];
__device__ float        g_psumsq[NBATCH * SLABS];
__device__ unsigned int g_pcnt[NBATCH * SLABS];
__device__ float        g_mean[NBATCH];
__device__ float        g_inv[NBATCH];
__device__ unsigned int g_bar;               // monotonic grid-barrier counter (never reset)

// Monotonic-counter grid barrier: replay-safe, no reset required.
__device__ __forceinline__ void grid_barrier() {
    __syncthreads();
    if (threadIdx.x == 0) {
        __threadfence();                                  // release
        unsigned int old = atomicAdd(&g_bar, 1u);
        unsigned int target = (old / NBLK + 1u) * NBLK;
        volatile unsigned int* p = &g_bar;
        long long spins = 0;
        while (*p < target) {
            __nanosleep(32);
            if (++spins > 300000000LL) break;             // bail instead of hang
        }
    }
    __syncthreads();
    __threadfence();                                      // acquire
}

__global__ __launch_bounds__(THREADS, 3)
void fused_masked_normalize(const float4* __restrict__ x, float4* __restrict__ out) {
    const int t    = threadIdx.x;
    const int lane = t & 31;
    const int warp = t >> 5;

    __shared__ float        sh_s[THREADS / 32];
    __shared__ float        sh_ss[THREADS / 32];
    __shared__ unsigned int sh_c[THREADS / 32];

    const int sub   = blockIdx.x / SLABS;     // 0..3: batch index within group
    const int slab  = blockIdx.x % SLABS;     // 0..110
    const int start = slab * SLAB_F4;
    const int end   = (start + SLAB_F4 < PER4) ? (start + SLAB_F4) : PER4;

    for (int s = 0; s <= GROUPS; s++) {
        const bool doR = (s < GROUPS);        // reduce group s
        const bool doN = (s > 0);             // normalize group s-1

        const int batch_r = s * BPG + sub;
        const int batch_n = (s - 1) * BPG + sub;
        const float4* __restrict__ xr = x   + (doR ? (size_t)batch_r * PER4 : 0);
        const float4* __restrict__ xn = x   + (doN ? (size_t)batch_n * PER4 : 0);
        float4*       __restrict__ on = out + (doN ? (size_t)batch_n * PER4 : 0);

        float mean = 0.f, inv = 0.f;
        if (doN) { mean = g_mean[batch_n]; inv = g_inv[batch_n]; }

        // Masked entries are exactly 0.0f -> sum/sumsq over ALL elements equal
        // the masked sums; only the count needs compares. Branch-free hot loop.
        float sa = 0.f, ssa = 0.f;
        unsigned int ca = 0;

        for (int base = start + t; base < end; base += THREADS * UN) {
            float4 r[UN], n[UN];
            bool   p[UN];
            #pragma unroll
            for (int k = 0; k < UN; k++) p[k] = (base + k * THREADS) < end;

            if (doR) {
                #pragma unroll
                for (int k = 0; k < UN; k++)
                    if (p[k]) r[k] = xr[base + k * THREADS];       // allocate in L2
            }
            if (doN) {
                #pragma unroll
                for (int k = 0; k < UN; k++)
                    if (p[k]) n[k] = __ldcs(&xn[base + k * THREADS]); // L2-hit, dead after
            }
            if (doR) {
                #pragma unroll
                for (int k = 0; k < UN; k++) {
                    if (p[k]) {
                        sa  += r[k].x + r[k].y + r[k].z + r[k].w;
                        ssa  = fmaf(r[k].x, r[k].x, ssa);
                        ssa  = fmaf(r[k].y, r[k].y, ssa);
                        ssa  = fmaf(r[k].z, r[k].z, ssa);
                        ssa  = fmaf(r[k].w, r[k].w, ssa);
                        ca  += (r[k].x != 0.f) + (r[k].y != 0.f) + (r[k].z != 0.f) + (r[k].w != 0.f);
                    }
                }
            }
            if (doN) {
                #pragma unroll
                for (int k = 0; k < UN; k++) {
                    if (p[k]) {
                        float4 o;
                        o.x = (n[k].x != 0.f) ? (n[k].x - mean) * inv : 0.f;
                        o.y = (n[k].y != 0.f) ? (n[k].y - mean) * inv : 0.f;
                        o.z = (n[k].z != 0.f) ? (n[k].z - mean) * inv : 0.f;
                        o.w = (n[k].w != 0.f) ? (n[k].w - mean) * inv : 0.f;
                        __stcs(&on[base + k * THREADS], o);        // don't evict resident x
                    }
                }
            }
        }

        if (doR) {
            // deterministic block reduce -> fixed slot [batch_r][slab]
            #pragma unroll
            for (int off = 16; off > 0; off >>= 1) {
                sa  += __shfl_xor_sync(0xFFFFFFFFu, sa,  off);
                ssa += __shfl_xor_sync(0xFFFFFFFFu, ssa, off);
                ca  += __shfl_xor_sync(0xFFFFFFFFu, ca,  off);
            }
            if (lane == 0) { sh_s[warp] = sa; sh_ss[warp] = ssa; sh_c[warp] = ca; }
            __syncthreads();
            if (warp == 0) {
                sa  = (lane < THREADS / 32) ? sh_s[lane]  : 0.f;
                ssa = (lane < THREADS / 32) ? sh_ss[lane] : 0.f;
                ca  = (lane < THREADS / 32) ? sh_c[lane]  : 0u;
                #pragma unroll
                for (int off = 8; off > 0; off >>= 1) {
                    sa  += __shfl_xor_sync(0xFFFFFFFFu, sa,  off);
                    ssa += __shfl_xor_sync(0xFFFFFFFFu, ssa, off);
                    ca  += __shfl_xor_sync(0xFFFFFFFFu, ca,  off);
                }
                if (lane == 0) {
                    const int idx = batch_r * SLABS + slab;
                    g_psum[idx] = sa; g_psumsq[idx] = ssa; g_pcnt[idx] = ca;
                }
            }
            __syncthreads();

            // ---- finalize group s stats before next superstep ----
            grid_barrier();
            if (blockIdx.x < BPG) {
                const int b = s * BPG + blockIdx.x;
                double ds = 0.0, dss = 0.0;
                unsigned long long dc = 0;
                if (t < SLABS) {
                    const int idx = b * SLABS + t;
                    ds  = (double)g_psum[idx];
                    dss = (double)g_psumsq[idx];
                    dc  = g_pcnt[idx];
                }
                #pragma unroll
                for (int off = 16; off > 0; off >>= 1) {
                    ds  += __shfl_xor_sync(0xFFFFFFFFu, ds,  off);
                    dss += __shfl_xor_sync(0xFFFFFFFFu, dss, off);
                    dc  += __shfl_xor_sync(0xFFFFFFFFu, dc,  off);
                }
                __shared__ double fs[THREADS / 32];
                __shared__ double fss[THREADS / 32];
                __shared__ unsigned long long fc[THREADS / 32];
                if (lane == 0) { fs[warp] = ds; fss[warp] = dss; fc[warp] = dc; }
                __syncthreads();
                if (t == 0) {
                    double S = 0.0, SS = 0.0; unsigned long long C = 0;
                    #pragma unroll
                    for (int w = 0; w < (SLABS + 31) / 32; w++) { S += fs[w]; SS += fss[w]; C += fc[w]; }
                    const double nn   = (double)C;
                    const double mu   = S / nn;
                    const double var  = (SS - S * S / nn) / (nn - 1.0);  // m2 term analytically 0
                    g_mean[b] = (float)mu;
                    g_inv[b]  = (float)(1.0 / (sqrt(var) + (double)EPS));
                }
                __syncthreads();
            }
            grid_barrier();
        }
    }
}

extern "C" void kernel_launch(void* const* d_in, const int* in_sizes, int n_in,
                              void* d_out, int out_size) {
    const float4* x   = (const float4*)d_in[0];
    float4*       out = (float4*)d_out;
    fused_masked_normalize<<<NBLK, THREADS>>>(x, out);
}

// round 10
// speedup vs baseline: 2.0263x; 2.0263x over previous
#include <cuda_runtime.h>
#include <cstdint>

#define EPS 1e-5f
#define NBATCH 16
#define PER4 (1024 * 1024)                      // float4s per batch (4M floats)

#define RED_THREADS 256
#define RED_BLOCKS 128                          // blocks per batch
#define RED_STRIDE (RED_BLOCKS * RED_THREADS)   // 32768
#define RED_ITERS (PER4 / RED_STRIDE)           // 32 per thread
#define RED_UNROLL 16                           // front-batched loads per step

#define NORM_THREADS 256
#define NORM_F4_PER_THREAD 8
#define NORM_F4_PER_BLOCK (NORM_THREADS * NORM_F4_PER_THREAD)   // 2048
#define NORM_BLOCKS (PER4 / NORM_F4_PER_BLOCK)                  // 512 per batch

// Scratch (allocation-free -> __device__ globals)
__device__ float        g_psum[NBATCH * RED_BLOCKS];
__device__ float        g_psumsq[NBATCH * RED_BLOCKS];
__device__ unsigned int g_pcnt[NBATCH * RED_BLOCKS];

// ---------------------------------------------------------------------------
// Pass 1: per-batch partial (sum, sumsq, nnz). Masked entries are exactly
// 0.0f, so sum/sumsq over ALL elements equal the masked sums -> branch-free.
// 16 front-batched LDG.128 per step for deep MLP.
// ---------------------------------------------------------------------------
__global__ __launch_bounds__(RED_THREADS)
void reduce_kernel(const float4* __restrict__ x) {
    const int b = blockIdx.y;
    const float4* xb = x + (size_t)b * PER4;

    float s = 0.f, ss = 0.f;
    unsigned int c = 0;

    const int base = blockIdx.x * RED_THREADS + threadIdx.x;

    #pragma unroll 1
    for (int j = 0; j < RED_ITERS; j += RED_UNROLL) {
        float4 v[RED_UNROLL];
        #pragma unroll
        for (int k = 0; k < RED_UNROLL; k++)
            v[k] = xb[base + (size_t)(j + k) * RED_STRIDE];
        #pragma unroll
        for (int k = 0; k < RED_UNROLL; k++) {
            s  += v[k].x + v[k].y + v[k].z + v[k].w;
            ss  = fmaf(v[k].x, v[k].x, ss);
            ss  = fmaf(v[k].y, v[k].y, ss);
            ss  = fmaf(v[k].z, v[k].z, ss);
            ss  = fmaf(v[k].w, v[k].w, ss);
            c  += (v[k].x != 0.f) + (v[k].y != 0.f) + (v[k].z != 0.f) + (v[k].w != 0.f);
        }
    }

    // deterministic block reduce
    #pragma unroll
    for (int off = 16; off > 0; off >>= 1) {
        s  += __shfl_xor_sync(0xFFFFFFFFu, s,  off);
        ss += __shfl_xor_sync(0xFFFFFFFFu, ss, off);
        c  += __shfl_xor_sync(0xFFFFFFFFu, c,  off);
    }

    __shared__ float        sh_s[RED_THREADS / 32];
    __shared__ float        sh_ss[RED_THREADS / 32];
    __shared__ unsigned int sh_c[RED_THREADS / 32];
    const int lane = threadIdx.x & 31;
    const int warp = threadIdx.x >> 5;
    if (lane == 0) { sh_s[warp] = s; sh_ss[warp] = ss; sh_c[warp] = c; }
    __syncthreads();

    if (warp == 0) {
        s  = (lane < RED_THREADS / 32) ? sh_s[lane]  : 0.f;
        ss = (lane < RED_THREADS / 32) ? sh_ss[lane] : 0.f;
        c  = (lane < RED_THREADS / 32) ? sh_c[lane]  : 0u;
        #pragma unroll
        for (int off = 4; off > 0; off >>= 1) {
            s  += __shfl_xor_sync(0xFFFFFFFFu, s,  off);
            ss += __shfl_xor_sync(0xFFFFFFFFu, ss, off);
            c  += __shfl_xor_sync(0xFFFFFFFFu, c,  off);
        }
        if (lane == 0) {
            const int idx = b * RED_BLOCKS + blockIdx.x;
            g_psum[idx]   = s;
            g_psumsq[idx] = ss;
            g_pcnt[idx]   = c;
        }
    }
}

// ---------------------------------------------------------------------------
// Pass 2: normalize. Each block first derives its batch's stats inline from
// the 128 partials (fixed-shape double-precision tree -> bit-deterministic,
// identical in every block; reads hit L2). Then 8 front-batched float4s per
// thread; plain loads + __stcs streaming stores.
// ---------------------------------------------------------------------------
__global__ __launch_bounds__(NORM_THREADS)
void normalize_kernel(const float4* __restrict__ x, float4* __restrict__ out) {
    const int b = blockIdx.y;

    __shared__ float sh_mean, sh_inv;

    if (threadIdx.x < 32) {
        const int lane = threadIdx.x;
        double s = 0.0, ss = 0.0;
        unsigned long long c = 0;
        #pragma unroll
        for (int k = 0; k < RED_BLOCKS / 32; k++) {
            const int idx = b * RED_BLOCKS + k * 32 + lane;
            s  += (double)g_psum[idx];
            ss += (double)g_psumsq[idx];
            c  += g_pcnt[idx];
        }
        #pragma unroll
        for (int off = 16; off > 0; off >>= 1) {
            s  += __shfl_xor_sync(0xFFFFFFFFu, s,  off);
            ss += __shfl_xor_sync(0xFFFFFFFFu, ss, off);
            c  += __shfl_xor_sync(0xFFFFFFFFu, c,  off);
        }
        if (lane == 0) {
            const double n    = (double)c;
            const double mean = s / n;
            const double var  = (ss - s * s / n) / (n - 1.0);  // m2 term analytically 0
            sh_mean = (float)mean;
            sh_inv  = (float)(1.0 / (sqrt(var) + (double)EPS));
        }
    }
    __syncthreads();

    const float mean = sh_mean;
    const float inv  = sh_inv;

    const size_t off = (size_t)b * PER4 + (size_t)blockIdx.x * NORM_F4_PER_BLOCK + threadIdx.x;

    float4 v[NORM_F4_PER_THREAD];
    #pragma unroll
    for (int k = 0; k < NORM_F4_PER_THREAD; k++)
        v[k] = x[off + (size_t)k * NORM_THREADS];

    #pragma unroll
    for (int k = 0; k < NORM_F4_PER_THREAD; k++) {
        float4 o;
        o.x = (v[k].x != 0.f) ? (v[k].x - mean) * inv : 0.f;
        o.y = (v[k].y != 0.f) ? (v[k].y - mean) * inv : 0.f;
        o.z = (v[k].z != 0.f) ? (v[k].z - mean) * inv : 0.f;
        o.w = (v[k].w != 0.f) ? (v[k].w - mean) * inv : 0.f;
        __stcs(&out[off + (size_t)k * NORM_THREADS], o);
    }
}

extern "C" void kernel_launch(void* const* d_in, const int* in_sizes, int n_in,
                              void* d_out, int out_size) {
    const float4* x   = (const float4*)d_in[0];
    float4*       out = (float4*)d_out;

    dim3 redGrid(RED_BLOCKS, NBATCH);
    reduce_kernel<<<redGrid, RED_THREADS>>>(x);

    dim3 normGrid(NORM_BLOCKS, NBATCH);
    normalize_kernel<<<normGrid, NORM_THREADS>>>(x, out);
}

// round 11
// speedup vs baseline: 2.0879x; 1.0304x over previous
#include <cuda_runtime.h>
#include <cstdint>

#define EPS 1e-5f
#define NBATCH 16
#define PER4 (1024 * 1024)                      // float4s per batch (4M floats)

#define RED_THREADS 256
#define RED_BLOCKS 128                          // blocks per batch -> 2048 total
#define RED_STRIDE (RED_BLOCKS * RED_THREADS)   // 32768
#define RED_ITERS (PER4 / RED_STRIDE)           // 32 per thread
#define RED_UNROLL 8                            // front-batched loads (R2-proven)

#define NORM_THREADS 256
#define NORM_F4_PER_THREAD 8
#define NORM_F4_PER_BLOCK (NORM_THREADS * NORM_F4_PER_THREAD)   // 2048
#define NORM_BLOCKS (PER4 / NORM_F4_PER_BLOCK)                  // 512 per batch

// Scratch (allocation-free -> __device__ globals)
__device__ float        g_psum[NBATCH * RED_BLOCKS];
__device__ float        g_psumsq[NBATCH * RED_BLOCKS];
__device__ unsigned int g_pcnt[NBATCH * RED_BLOCKS];

// ---------------------------------------------------------------------------
// Pass 1: per-batch partial (sum, sumsq, nnz). Masked entries are exactly
// 0.0f, so sum/sumsq over ALL elements equal the masked sums -> branch-free.
// 8 front-batched LDG.128 per step (R2-proven: 81.9% DRAM, 30 regs).
// ---------------------------------------------------------------------------
__global__ __launch_bounds__(RED_THREADS)
void reduce_kernel(const float4* __restrict__ x) {
    const int b = blockIdx.y;
    const float4* xb = x + (size_t)b * PER4;

    float s = 0.f, ss = 0.f;
    unsigned int c = 0;

    const int base = blockIdx.x * RED_THREADS + threadIdx.x;

    #pragma unroll 1
    for (int j = 0; j < RED_ITERS; j += RED_UNROLL) {
        float4 v[RED_UNROLL];
        #pragma unroll
        for (int k = 0; k < RED_UNROLL; k++)
            v[k] = xb[base + (size_t)(j + k) * RED_STRIDE];
        #pragma unroll
        for (int k = 0; k < RED_UNROLL; k++) {
            s  += v[k].x + v[k].y + v[k].z + v[k].w;
            ss  = fmaf(v[k].x, v[k].x, ss);
            ss  = fmaf(v[k].y, v[k].y, ss);
            ss  = fmaf(v[k].z, v[k].z, ss);
            ss  = fmaf(v[k].w, v[k].w, ss);
            c  += (v[k].x != 0.f) + (v[k].y != 0.f) + (v[k].z != 0.f) + (v[k].w != 0.f);
        }
    }

    // deterministic block reduce
    #pragma unroll
    for (int off = 16; off > 0; off >>= 1) {
        s  += __shfl_xor_sync(0xFFFFFFFFu, s,  off);
        ss += __shfl_xor_sync(0xFFFFFFFFu, ss, off);
        c  += __shfl_xor_sync(0xFFFFFFFFu, c,  off);
    }

    __shared__ float        sh_s[RED_THREADS / 32];
    __shared__ float        sh_ss[RED_THREADS / 32];
    __shared__ unsigned int sh_c[RED_THREADS / 32];
    const int lane = threadIdx.x & 31;
    const int warp = threadIdx.x >> 5;
    if (lane == 0) { sh_s[warp] = s; sh_ss[warp] = ss; sh_c[warp] = c; }
    __syncthreads();

    if (warp == 0) {
        s  = (lane < RED_THREADS / 32) ? sh_s[lane]  : 0.f;
        ss = (lane < RED_THREADS / 32) ? sh_ss[lane] : 0.f;
        c  = (lane < RED_THREADS / 32) ? sh_c[lane]  : 0u;
        #pragma unroll
        for (int off = 4; off > 0; off >>= 1) {
            s  += __shfl_xor_sync(0xFFFFFFFFu, s,  off);
            ss += __shfl_xor_sync(0xFFFFFFFFu, ss, off);
            c  += __shfl_xor_sync(0xFFFFFFFFu, c,  off);
        }
        if (lane == 0) {
            const int idx = b * RED_BLOCKS + blockIdx.x;
            g_psum[idx]   = s;
            g_psumsq[idx] = ss;
            g_pcnt[idx]   = c;
        }
    }
}

// ---------------------------------------------------------------------------
// Pass 2: normalize. The 8 x-loads are issued FIRST (independent of stats);
// warp 0 then derives the batch stats inline from the 128 partials (fixed-
// shape double tree -> bit-deterministic, L2-hit reads) while the x-loads are
// in flight. Plain loads + __stcs streaming stores.
// ---------------------------------------------------------------------------
__global__ __launch_bounds__(NORM_THREADS)
void normalize_kernel(const float4* __restrict__ x, float4* __restrict__ out) {
    const int b = blockIdx.y;
    const size_t off = (size_t)b * PER4 + (size_t)blockIdx.x * NORM_F4_PER_BLOCK + threadIdx.x;

    // issue data loads first — they overlap the stats preamble below
    float4 v[NORM_F4_PER_THREAD];
    #pragma unroll
    for (int k = 0; k < NORM_F4_PER_THREAD; k++)
        v[k] = x[off + (size_t)k * NORM_THREADS];

    __shared__ float sh_mean, sh_inv;
    if (threadIdx.x < 32) {
        const int lane = threadIdx.x;
        double s = 0.0, ss = 0.0;
        unsigned long long c = 0;
        #pragma unroll
        for (int k = 0; k < RED_BLOCKS / 32; k++) {
            const int idx = b * RED_BLOCKS + k * 32 + lane;
            s  += (double)g_psum[idx];
            ss += (double)g_psumsq[idx];
            c  += g_pcnt[idx];
        }
        #pragma unroll
        for (int o = 16; o > 0; o >>= 1) {
            s  += __shfl_xor_sync(0xFFFFFFFFu, s,  o);
            ss += __shfl_xor_sync(0xFFFFFFFFu, ss, o);
            c  += __shfl_xor_sync(0xFFFFFFFFu, c,  o);
        }
        if (lane == 0) {
            const double n    = (double)c;
            const double mean = s / n;
            const double var  = (ss - s * s / n) / (n - 1.0);  // m2 term analytically 0
            sh_mean = (float)mean;
            sh_inv  = (float)(1.0 / (sqrt(var) + (double)EPS));
        }
    }
    __syncthreads();

    const float mean = sh_mean;
    const float inv  = sh_inv;

    #pragma unroll
    for (int k = 0; k < NORM_F4_PER_THREAD; k++) {
        float4 o;
        o.x = (v[k].x != 0.f) ? (v[k].x - mean) * inv : 0.f;
        o.y = (v[k].y != 0.f) ? (v[k].y - mean) * inv : 0.f;
        o.z = (v[k].z != 0.f) ? (v[k].z - mean) * inv : 0.f;
        o.w = (v[k].w != 0.f) ? (v[k].w - mean) * inv : 0.f;
        __stcs(&out[off + (size_t)k * NORM_THREADS], o);
    }
}

extern "C" void kernel_launch(void* const* d_in, const int* in_sizes, int n_in,
                              void* d_out, int out_size) {
    const float4* x   = (const float4*)d_in[0];
    float4*       out = (float4*)d_out;

    dim3 redGrid(RED_BLOCKS, NBATCH);
    reduce_kernel<<<redGrid, RED_THREADS>>>(x);

    dim3 normGrid(NORM_BLOCKS, NBATCH);
    normalize_kernel<<<normGrid, NORM_THREADS>>>(x, out);
}